// round 2
// baseline (speedup 1.0000x reference)
#include <cuda_runtime.h>
#include <math.h>

#define LL 2048
#define DM 2048
#define NH 32
#define HD 64
#define SSTR 65   // smem row stride (floats) for the attention tiles

// ---------------- scratch (static device globals: allocation-free) -----------
__device__ float g_q[LL * DM];
__device__ float g_k[LL * DM];
__device__ float g_v[LL * DM];
__device__ float g_qr[LL * DM];
__device__ float g_kr[LL * DM];
__device__ float g_attn[LL * DM];

// ---------------- SGEMM: C[M,N] = A[M,K] * B[N,K]^T  (both row-major) --------
// 128x128 block tile, BK=8, 8x8 per thread (split 4+4 at 64 offset), 256 thr.
__global__ __launch_bounds__(256) void sgemm_nt(
    const float* __restrict__ A, const float* __restrict__ B,
    float* __restrict__ C, int M, int N, int K)
{
    __shared__ float As[8][128];
    __shared__ float Bs[8][128];
    const int tid = threadIdx.x;
    const int tx = tid & 15, ty = tid >> 4;
    const int m0 = blockIdx.y * 128, n0 = blockIdx.x * 128;
    const int lr = tid >> 1;         // 0..127
    const int lc = (tid & 1) * 4;    // 0 or 4
    const float* Ap = A + (size_t)(m0 + lr) * K + lc;
    const float* Bp = B + (size_t)(n0 + lr) * K + lc;

    float acc[8][8];
#pragma unroll
    for (int i = 0; i < 8; i++)
#pragma unroll
        for (int j = 0; j < 8; j++) acc[i][j] = 0.f;

    for (int k0 = 0; k0 < K; k0 += 8) {
        float4 av = *(const float4*)(Ap + k0);
        float4 bv = *(const float4*)(Bp + k0);
        __syncthreads();
        As[lc + 0][lr] = av.x; As[lc + 1][lr] = av.y;
        As[lc + 2][lr] = av.z; As[lc + 3][lr] = av.w;
        Bs[lc + 0][lr] = bv.x; Bs[lc + 1][lr] = bv.y;
        Bs[lc + 2][lr] = bv.z; Bs[lc + 3][lr] = bv.w;
        __syncthreads();
#pragma unroll
        for (int kk = 0; kk < 8; kk++) {
            float a[8], b[8];
            *(float4*)&a[0] = *(const float4*)&As[kk][ty * 4];
            *(float4*)&a[4] = *(const float4*)&As[kk][64 + ty * 4];
            *(float4*)&b[0] = *(const float4*)&Bs[kk][tx * 4];
            *(float4*)&b[4] = *(const float4*)&Bs[kk][64 + tx * 4];
#pragma unroll
            for (int i = 0; i < 8; i++)
#pragma unroll
                for (int j = 0; j < 8; j++)
                    acc[i][j] = fmaf(a[i], b[j], acc[i][j]);
        }
    }

#pragma unroll
    for (int bi = 0; bi < 2; bi++)
#pragma unroll
        for (int i = 0; i < 4; i++) {
            int r = m0 + bi * 64 + ty * 4 + i;
#pragma unroll
            for (int bj = 0; bj < 2; bj++) {
                float4 v = make_float4(acc[bi * 4 + i][bj * 4 + 0],
                                       acc[bi * 4 + i][bj * 4 + 1],
                                       acc[bi * 4 + i][bj * 4 + 2],
                                       acc[bi * 4 + i][bj * 4 + 3]);
                *(float4*)&C[(size_t)r * N + n0 + bj * 64 + tx * 4] = v;
            }
        }
}

// ---------------- RoPE (fp32, matches jnp fp32 trig path) --------------------
// out[j]    = x[2j]*cos - x[2j+1]*sin
// out[32+j] = x[2j]*sin + x[2j+1]*cos        (per head, j in [0,32))
// mode 0: q path (reads g_q, writes g_qr, folds 1/sqrt(64))
// mode 1: k path (reads g_k, writes g_kr)
__global__ void rope_kernel(int mode)
{
    int idx = blockIdx.x * blockDim.x + threadIdx.x;
    if (idx >= LL * NH * 32) return;
    int j = idx & 31;
    int h = (idx >> 5) & 31;
    int l = idx >> 10;
    const float* in = mode ? g_k : g_q;
    float* out = mode ? g_kr : g_qr;
    float oscale = mode ? 1.0f : 0.125f;
    // inv_freq = 10000^(-(2j)/64) ; ln(10000)=9.210340371976184
    float invf = expf(-((float)(2 * j) * (1.0f / 64.0f)) * 9.210340371976184f);
    float ang = (float)l * invf;
    float s, c;
    sincosf(ang, &s, &c);
    const float* row = in + (size_t)l * DM + h * HD;
    float x1 = row[2 * j], x2 = row[2 * j + 1];
    float* orow = out + (size_t)l * DM + h * HD;
    orow[j] = (x1 * c - x2 * s) * oscale;
    orow[32 + j] = (x1 * s + x2 * c) * oscale;
}

// ---------------- Flash attention, fp32, 64-q x 64-k tiles -------------------
// block = (q-tile, head). 256 threads as 16x16, each computes 4x4 of S and O.
// 1/sqrt(64) already folded into Q by the RoPE kernel.
// Reads g_qr / g_kr / g_v, writes g_attn.
__global__ __launch_bounds__(256) void flash_attn(const int* __restrict__ mask)
{
    extern __shared__ float sm[];
    float* Qs = sm;
    float* Ks = sm + 64 * SSTR;
    float* Vs = sm + 2 * 64 * SSTR;
    float* Ps = sm + 3 * 64 * SSTR;

    const int tid = threadIdx.x;
    const int tx = tid & 15, ty = tid >> 4;
    const int head = blockIdx.y;
    const int q0 = blockIdx.x * 64;

    for (int i = tid; i < 64 * 64; i += 256) {
        int r = i >> 6, c = i & 63;
        Qs[r * SSTR + c] = g_qr[(size_t)(q0 + r) * DM + head * HD + c];
    }

    float o[4][4];
    float mrow[4], lrow[4];
#pragma unroll
    for (int i = 0; i < 4; i++) {
        mrow[i] = -INFINITY;
        lrow[i] = 0.f;
#pragma unroll
        for (int j = 0; j < 4; j++) o[i][j] = 0.f;
    }

    for (int kt = 0; kt < LL / 64; kt++) {
        __syncthreads();  // previous iter done with Ks/Vs/Ps
        for (int i = tid; i < 64 * 64; i += 256) {
            int r = i >> 6, c = i & 63;
            size_t g = (size_t)(kt * 64 + r) * DM + head * HD + c;
            Ks[r * SSTR + c] = g_kr[g];
            Vs[r * SSTR + c] = g_v[g];
        }
        __syncthreads();

        // S = Q * K^T (scale pre-folded into Q)
        float s[4][4];
#pragma unroll
        for (int i = 0; i < 4; i++)
#pragma unroll
            for (int j = 0; j < 4; j++) s[i][j] = 0.f;

#pragma unroll 4
        for (int c = 0; c < 64; c++) {
            float qa[4], kb[4];
#pragma unroll
            for (int i = 0; i < 4; i++) qa[i] = Qs[(ty * 4 + i) * SSTR + c];
#pragma unroll
            for (int j = 0; j < 4; j++) kb[j] = Ks[(tx * 4 + j) * SSTR + c];
#pragma unroll
            for (int i = 0; i < 4; i++)
#pragma unroll
                for (int j = 0; j < 4; j++)
                    s[i][j] = fmaf(qa[i], kb[j], s[i][j]);
        }

        // mask (reference: masked -> -1e9 after scaling)
#pragma unroll
        for (int j = 0; j < 4; j++) {
            if (mask[kt * 64 + tx * 4 + j] == 0) {
#pragma unroll
                for (int i = 0; i < 4; i++) s[i][j] = -1e9f;
            }
        }

        // online softmax per q-row (reduce across the 16 tx lanes)
#pragma unroll
        for (int i = 0; i < 4; i++) {
            float mx = fmaxf(fmaxf(s[i][0], s[i][1]), fmaxf(s[i][2], s[i][3]));
#pragma unroll
            for (int off = 8; off >= 1; off >>= 1)
                mx = fmaxf(mx, __shfl_xor_sync(0xffffffffu, mx, off));
            float mnew = fmaxf(mrow[i], mx);
            float alpha = __expf(mrow[i] - mnew);
            float psum = 0.f;
#pragma unroll
            for (int j = 0; j < 4; j++) {
                float p = __expf(s[i][j] - mnew);
                s[i][j] = p;
                psum += p;
            }
#pragma unroll
            for (int off = 8; off >= 1; off >>= 1)
                psum += __shfl_xor_sync(0xffffffffu, psum, off);
            lrow[i] = lrow[i] * alpha + psum;
            mrow[i] = mnew;
#pragma unroll
            for (int j = 0; j < 4; j++) {
                o[i][j] *= alpha;
                Ps[(ty * 4 + i) * SSTR + tx * 4 + j] = s[i][j];
            }
        }
        __syncthreads();  // all P written before PV

        // O += P * V
#pragma unroll 4
        for (int k = 0; k < 64; k++) {
            float pv[4], vv[4];
#pragma unroll
            for (int i = 0; i < 4; i++) pv[i] = Ps[(ty * 4 + i) * SSTR + k];
#pragma unroll
            for (int j = 0; j < 4; j++) vv[j] = Vs[k * SSTR + tx * 4 + j];
#pragma unroll
            for (int i = 0; i < 4; i++)
#pragma unroll
                for (int j = 0; j < 4; j++)
                    o[i][j] = fmaf(pv[i], vv[j], o[i][j]);
        }
    }

#pragma unroll
    for (int i = 0; i < 4; i++) {
        float inv = 1.f / lrow[i];
#pragma unroll
        for (int j = 0; j < 4; j++)
            g_attn[(size_t)(q0 + ty * 4 + i) * DM + head * HD + tx * 4 + j] =
                o[i][j] * inv;
    }
}

// ---------------- launch ------------------------------------------------------
extern "C" void kernel_launch(void* const* d_in, const int* in_sizes, int n_in,
                              void* d_out, int out_size)
{
    const float* x = (const float*)d_in[0];
    const int* mask = (const int*)d_in[1];
    const float* Wq = (const float*)d_in[2];
    const float* Wk = (const float*)d_in[3];
    const float* Wv = (const float*)d_in[4];
    const float* Wo = (const float*)d_in[5];
    float* out = (float*)d_out;

    // Device scratch pointers: resolved without cudaGetSymbolAddress by
    // letting kernels reference the globals directly where possible; the
    // SGEMM kernels still need raw pointers, taken via the symbol API once.
    static float *q = nullptr, *k = nullptr, *v = nullptr, *attn = nullptr;
    if (!q) {
        cudaGetSymbolAddress((void**)&q, g_q);
        cudaGetSymbolAddress((void**)&k, g_k);
        cudaGetSymbolAddress((void**)&v, g_v);
        cudaGetSymbolAddress((void**)&attn, g_attn);
        const int flash_smem = 4 * 64 * SSTR * (int)sizeof(float);  // 66560 B
        cudaFuncSetAttribute(flash_attn,
                             cudaFuncAttributeMaxDynamicSharedMemorySize,
                             flash_smem);
    }
    const int flash_smem = 4 * 64 * SSTR * (int)sizeof(float);

    dim3 gg(DM / 128, LL / 128);
    sgemm_nt<<<gg, 256>>>(x, Wq, q, LL, DM, DM);
    sgemm_nt<<<gg, 256>>>(x, Wk, k, LL, DM, DM);
    sgemm_nt<<<gg, 256>>>(x, Wv, v, LL, DM, DM);

    const int nrope = LL * NH * 32;
    rope_kernel<<<(nrope + 255) / 256, 256>>>(0);
    rope_kernel<<<(nrope + 255) / 256, 256>>>(1);

    flash_attn<<<dim3(LL / 64, NH), 256, flash_smem>>>(mask);

    sgemm_nt<<<gg, 256>>>(attn, Wo, out, LL, DM, DM);
}

// round 3
// speedup vs baseline: 1.4051x; 1.4051x over previous
#include <cuda_runtime.h>
#include <cuda_bf16.h>
#include <math.h>

#define LL 2048
#define DM 2048
#define NH 32
#define HD 64
#define SSTR 65   // smem row stride (floats) for the attention tiles
#define PADU 20   // u32 row stride for bf16x2-packed GEMM smem (conflict-free frags)

// ---------------- scratch (static device globals: allocation-free) -----------
__device__ float g_q[LL * DM];
__device__ float g_k[LL * DM];
__device__ float g_v[LL * DM];
__device__ float g_qr[LL * DM];
__device__ float g_kr[LL * DM];
__device__ float g_attn[LL * DM];

// ---------------- helpers ----------------------------------------------------
__device__ __forceinline__ void split2(float x, float y,
                                       unsigned& hi, unsigned& lo)
{
    __nv_bfloat16 hx = __float2bfloat16(x);
    __nv_bfloat16 hy = __float2bfloat16(y);
    float rx = x - __bfloat162float(hx);
    float ry = y - __bfloat162float(hy);
    __nv_bfloat162 h = __halves2bfloat162(hx, hy);
    __nv_bfloat162 l = __halves2bfloat162(__float2bfloat16(rx),
                                          __float2bfloat16(ry));
    hi = *reinterpret_cast<unsigned*>(&h);
    lo = *reinterpret_cast<unsigned*>(&l);
}

__device__ __forceinline__ void mma_bf16(float* d, const unsigned* a,
                                         unsigned b0, unsigned b1)
{
    asm volatile(
        "mma.sync.aligned.m16n8k16.row.col.f32.bf16.bf16.f32 "
        "{%0,%1,%2,%3},{%4,%5,%6,%7},{%8,%9},{%0,%1,%2,%3};\n"
        : "+f"(d[0]), "+f"(d[1]), "+f"(d[2]), "+f"(d[3])
        : "r"(a[0]), "r"(a[1]), "r"(a[2]), "r"(a[3]), "r"(b0), "r"(b1));
}

// ---------------- bf16x3 tensor-core GEMM: C = A[M,K] * B[N,K]^T -------------
// 128x128 block tile, BK=32, 256 threads = 8 warps (2x4), warp tile 64x32.
// fp32 inputs are split hi/lo ONCE in the smem producer; consumers do plain
// LDS.32 of packed bf16x2 and issue 3 HMMA per (tile, k16): hh + hl + lh.
__global__ __launch_bounds__(256) void gemm_bf16x3(
    const float* __restrict__ A, const float* __restrict__ B,
    float* __restrict__ C, int M, int N, int K)
{
    __shared__ unsigned As_hi[128 * PADU];
    __shared__ unsigned As_lo[128 * PADU];
    __shared__ unsigned Bs_hi[128 * PADU];
    __shared__ unsigned Bs_lo[128 * PADU];

    const int tid = threadIdx.x;
    const int wid = tid >> 5, lane = tid & 31;
    const int wm = wid >> 2, wn = wid & 3;          // 2 x 4 warp grid
    const int m0 = blockIdx.y * 128, n0 = blockIdx.x * 128;
    const int lr = lane >> 2, lc = lane & 3;

    float acc[4][4][4];
#pragma unroll
    for (int mt = 0; mt < 4; mt++)
#pragma unroll
        for (int nt = 0; nt < 4; nt++)
#pragma unroll
            for (int i = 0; i < 4; i++) acc[mt][nt][i] = 0.f;

    // producer indexing: 1024 float4 per tile, 4 per thread
    const int pr = tid >> 1;                // paired with t-loop below
    for (int k0 = 0; k0 < K; k0 += 32) {
        __syncthreads();
#pragma unroll
        for (int t = 0; t < 4; t++) {
            int idx = tid + t * 256;        // 0..1023
            int r = idx >> 3;               // 0..127
            int c4 = (idx & 7) * 4;         // 0,4,..,28
            const float4 av = *(const float4*)(A + (size_t)(m0 + r) * K + k0 + c4);
            unsigned h0, l0, h1, l1;
            split2(av.x, av.y, h0, l0);
            split2(av.z, av.w, h1, l1);
            int sa = r * PADU + (c4 >> 1);
            As_hi[sa] = h0; As_hi[sa + 1] = h1;
            As_lo[sa] = l0; As_lo[sa + 1] = l1;
            const float4 bv = *(const float4*)(B + (size_t)(n0 + r) * K + k0 + c4);
            split2(bv.x, bv.y, h0, l0);
            split2(bv.z, bv.w, h1, l1);
            Bs_hi[sa] = h0; Bs_hi[sa + 1] = h1;
            Bs_lo[sa] = l0; Bs_lo[sa + 1] = l1;
        }
        __syncthreads();

#pragma unroll
        for (int kh = 0; kh < 2; kh++) {
            // A fragments for 4 m-tiles (hi and lo)
            unsigned afh[4][4], afl[4][4];
#pragma unroll
            for (int mt = 0; mt < 4; mt++) {
                int r = wm * 64 + mt * 16 + lr;
                int base = r * PADU + kh * 8 + lc;
                afh[mt][0] = As_hi[base];
                afh[mt][1] = As_hi[base + 8 * PADU];
                afh[mt][2] = As_hi[base + 4];
                afh[mt][3] = As_hi[base + 8 * PADU + 4];
                afl[mt][0] = As_lo[base];
                afl[mt][1] = As_lo[base + 8 * PADU];
                afl[mt][2] = As_lo[base + 4];
                afl[mt][3] = As_lo[base + 8 * PADU + 4];
            }
#pragma unroll
            for (int nt = 0; nt < 4; nt++) {
                int n = wn * 32 + nt * 8 + lr;
                int base = n * PADU + kh * 8 + lc;
                unsigned bh0 = Bs_hi[base], bh1 = Bs_hi[base + 4];
                unsigned bl0 = Bs_lo[base], bl1 = Bs_lo[base + 4];
#pragma unroll
                for (int mt = 0; mt < 4; mt++) {
                    mma_bf16(acc[mt][nt], afh[mt], bh0, bh1);
                    mma_bf16(acc[mt][nt], afh[mt], bl0, bl1);
                    mma_bf16(acc[mt][nt], afl[mt], bh0, bh1);
                }
            }
        }
    }
    (void)pr;

    // epilogue: float2 stores
    const int rbase = m0 + wm * 64 + lr;
    const int cbase = n0 + wn * 32 + lc * 2;
#pragma unroll
    for (int mt = 0; mt < 4; mt++)
#pragma unroll
        for (int nt = 0; nt < 4; nt++) {
            int r = rbase + mt * 16;
            int c = cbase + nt * 8;
            *(float2*)&C[(size_t)r * N + c] =
                make_float2(acc[mt][nt][0], acc[mt][nt][1]);
            *(float2*)&C[(size_t)(r + 8) * N + c] =
                make_float2(acc[mt][nt][2], acc[mt][nt][3]);
        }
}

// ---------------- RoPE (fp32, matches jnp fp32 trig path) --------------------
__global__ void rope_kernel(int mode)
{
    int idx = blockIdx.x * blockDim.x + threadIdx.x;
    if (idx >= LL * NH * 32) return;
    int j = idx & 31;
    int h = (idx >> 5) & 31;
    int l = idx >> 10;
    const float* in = mode ? g_k : g_q;
    float* out = mode ? g_kr : g_qr;
    float oscale = mode ? 1.0f : 0.125f;
    float invf = expf(-((float)(2 * j) * (1.0f / 64.0f)) * 9.210340371976184f);
    float ang = (float)l * invf;
    float s, c;
    sincosf(ang, &s, &c);
    const float* row = in + (size_t)l * DM + h * HD;
    float x1 = row[2 * j], x2 = row[2 * j + 1];
    float* orow = out + (size_t)l * DM + h * HD;
    orow[j] = (x1 * c - x2 * s) * oscale;
    orow[32 + j] = (x1 * s + x2 * c) * oscale;
}

// ---------------- Flash attention, fp32, 64-q x 64-k tiles -------------------
__global__ __launch_bounds__(256) void flash_attn(const int* __restrict__ mask)
{
    extern __shared__ float sm[];
    float* Qs = sm;
    float* Ks = sm + 64 * SSTR;
    float* Vs = sm + 2 * 64 * SSTR;
    float* Ps = sm + 3 * 64 * SSTR;

    const int tid = threadIdx.x;
    const int tx = tid & 15, ty = tid >> 4;
    const int head = blockIdx.y;
    const int q0 = blockIdx.x * 64;

    for (int i = tid; i < 64 * 64; i += 256) {
        int r = i >> 6, c = i & 63;
        Qs[r * SSTR + c] = g_qr[(size_t)(q0 + r) * DM + head * HD + c];
    }

    float o[4][4];
    float mrow[4], lrow[4];
#pragma unroll
    for (int i = 0; i < 4; i++) {
        mrow[i] = -INFINITY;
        lrow[i] = 0.f;
#pragma unroll
        for (int j = 0; j < 4; j++) o[i][j] = 0.f;
    }

    for (int kt = 0; kt < LL / 64; kt++) {
        __syncthreads();
        for (int i = tid; i < 64 * 64; i += 256) {
            int r = i >> 6, c = i & 63;
            size_t g = (size_t)(kt * 64 + r) * DM + head * HD + c;
            Ks[r * SSTR + c] = g_kr[g];
            Vs[r * SSTR + c] = g_v[g];
        }
        __syncthreads();

        float s[4][4];
#pragma unroll
        for (int i = 0; i < 4; i++)
#pragma unroll
            for (int j = 0; j < 4; j++) s[i][j] = 0.f;

#pragma unroll 4
        for (int c = 0; c < 64; c++) {
            float qa[4], kb[4];
#pragma unroll
            for (int i = 0; i < 4; i++) qa[i] = Qs[(ty * 4 + i) * SSTR + c];
#pragma unroll
            for (int j = 0; j < 4; j++) kb[j] = Ks[(tx * 4 + j) * SSTR + c];
#pragma unroll
            for (int i = 0; i < 4; i++)
#pragma unroll
                for (int j = 0; j < 4; j++)
                    s[i][j] = fmaf(qa[i], kb[j], s[i][j]);
        }

#pragma unroll
        for (int j = 0; j < 4; j++) {
            if (mask[kt * 64 + tx * 4 + j] == 0) {
#pragma unroll
                for (int i = 0; i < 4; i++) s[i][j] = -1e9f;
            }
        }

#pragma unroll
        for (int i = 0; i < 4; i++) {
            float mx = fmaxf(fmaxf(s[i][0], s[i][1]), fmaxf(s[i][2], s[i][3]));
#pragma unroll
            for (int off = 8; off >= 1; off >>= 1)
                mx = fmaxf(mx, __shfl_xor_sync(0xffffffffu, mx, off));
            float mnew = fmaxf(mrow[i], mx);
            float alpha = __expf(mrow[i] - mnew);
            float psum = 0.f;
#pragma unroll
            for (int j = 0; j < 4; j++) {
                float p = __expf(s[i][j] - mnew);
                s[i][j] = p;
                psum += p;
            }
#pragma unroll
            for (int off = 8; off >= 1; off >>= 1)
                psum += __shfl_xor_sync(0xffffffffu, psum, off);
            lrow[i] = lrow[i] * alpha + psum;
            mrow[i] = mnew;
#pragma unroll
            for (int j = 0; j < 4; j++) {
                o[i][j] *= alpha;
                Ps[(ty * 4 + i) * SSTR + tx * 4 + j] = s[i][j];
            }
        }
        __syncthreads();

#pragma unroll 4
        for (int k = 0; k < 64; k++) {
            float pv[4], vv[4];
#pragma unroll
            for (int i = 0; i < 4; i++) pv[i] = Ps[(ty * 4 + i) * SSTR + k];
#pragma unroll
            for (int j = 0; j < 4; j++) vv[j] = Vs[k * SSTR + tx * 4 + j];
#pragma unroll
            for (int i = 0; i < 4; i++)
#pragma unroll
                for (int j = 0; j < 4; j++)
                    o[i][j] = fmaf(pv[i], vv[j], o[i][j]);
        }
    }

#pragma unroll
    for (int i = 0; i < 4; i++) {
        float inv = 1.f / lrow[i];
#pragma unroll
        for (int j = 0; j < 4; j++)
            g_attn[(size_t)(q0 + ty * 4 + i) * DM + head * HD + tx * 4 + j] =
                o[i][j] * inv;
    }
}

// ---------------- launch ------------------------------------------------------
extern "C" void kernel_launch(void* const* d_in, const int* in_sizes, int n_in,
                              void* d_out, int out_size)
{
    const float* x = (const float*)d_in[0];
    const int* mask = (const int*)d_in[1];
    const float* Wq = (const float*)d_in[2];
    const float* Wk = (const float*)d_in[3];
    const float* Wv = (const float*)d_in[4];
    const float* Wo = (const float*)d_in[5];
    float* out = (float*)d_out;

    static float *q = nullptr, *k = nullptr, *v = nullptr, *attn = nullptr;
    if (!q) {
        cudaGetSymbolAddress((void**)&q, g_q);
        cudaGetSymbolAddress((void**)&k, g_k);
        cudaGetSymbolAddress((void**)&v, g_v);
        cudaGetSymbolAddress((void**)&attn, g_attn);
        const int flash_smem = 4 * 64 * SSTR * (int)sizeof(float);  // 66560 B
        cudaFuncSetAttribute(flash_attn,
                             cudaFuncAttributeMaxDynamicSharedMemorySize,
                             flash_smem);
    }
    const int flash_smem = 4 * 64 * SSTR * (int)sizeof(float);

    dim3 gg(DM / 128, LL / 128);
    gemm_bf16x3<<<gg, 256>>>(x, Wq, q, LL, DM, DM);
    gemm_bf16x3<<<gg, 256>>>(x, Wk, k, LL, DM, DM);
    gemm_bf16x3<<<gg, 256>>>(x, Wv, v, LL, DM, DM);

    const int nrope = LL * NH * 32;
    rope_kernel<<<(nrope + 255) / 256, 256>>>(0);
    rope_kernel<<<(nrope + 255) / 256, 256>>>(1);

    flash_attn<<<dim3(LL / 64, NH), 256, flash_smem>>>(mask);

    gemm_bf16x3<<<gg, 256>>>(attn, Wo, out, LL, DM, DM);
}

// round 4
// speedup vs baseline: 2.1009x; 1.4952x over previous
#include <cuda_runtime.h>
#include <cuda_bf16.h>
#include <math.h>

#define LL 2048
#define DM 2048
#define NH 32
#define HD 64
#define PADU 20   // u32 row stride for GEMM smem
#define AST 35    // u32 row stride for attention smem tiles (conflict-free frags)

// ---------------- scratch (static device globals: allocation-free) -----------
__device__ float g_attn[LL * DM];
__device__ __nv_bfloat16 g_qh[LL * DM], g_ql[LL * DM];   // roped Q (hi/lo), scale folded
__device__ __nv_bfloat16 g_kh[LL * DM], g_kl[LL * DM];   // roped K (hi/lo)
__device__ __nv_bfloat16 g_vth[LL * DM], g_vtl[LL * DM]; // V transposed: [NH][HD][LL]

// ---------------- helpers ----------------------------------------------------
__device__ __forceinline__ void split2(float x, float y,
                                       unsigned& hi, unsigned& lo)
{
    __nv_bfloat16 hx = __float2bfloat16(x);
    __nv_bfloat16 hy = __float2bfloat16(y);
    float rx = x - __bfloat162float(hx);
    float ry = y - __bfloat162float(hy);
    __nv_bfloat162 h = __halves2bfloat162(hx, hy);
    __nv_bfloat162 l = __halves2bfloat162(__float2bfloat16(rx),
                                          __float2bfloat16(ry));
    hi = *reinterpret_cast<unsigned*>(&h);
    lo = *reinterpret_cast<unsigned*>(&l);
}

__device__ __forceinline__ void split1(float x, __nv_bfloat16& h, __nv_bfloat16& l)
{
    h = __float2bfloat16(x);
    l = __float2bfloat16(x - __bfloat162float(h));
}

__device__ __forceinline__ void mma_bf16(float* d, const unsigned* a,
                                         unsigned b0, unsigned b1)
{
    asm volatile(
        "mma.sync.aligned.m16n8k16.row.col.f32.bf16.bf16.f32 "
        "{%0,%1,%2,%3},{%4,%5,%6,%7},{%8,%9},{%0,%1,%2,%3};\n"
        : "+f"(d[0]), "+f"(d[1]), "+f"(d[2]), "+f"(d[3])
        : "r"(a[0]), "r"(a[1]), "r"(a[2]), "r"(a[3]), "r"(b0), "r"(b1));
}

// ---------------- bf16x3 tensor-core GEMM: C = A[M,K] * B[N,K]^T -------------
// EPI 0: plain fp32 C.  EPI 1: rope+split -> g_qh/g_ql (scale 1/8).
// EPI 2: rope+split -> g_kh/g_kl.  EPI 3: split+per-head transpose -> g_vth/l.
template <int EPI>
__global__ __launch_bounds__(256) void gemm_bf16x3(
    const float* __restrict__ A, const float* __restrict__ B,
    float* __restrict__ C, int M, int N, int K)
{
    __shared__ unsigned As_hi[128 * PADU];
    __shared__ unsigned As_lo[128 * PADU];
    __shared__ unsigned Bs_hi[128 * PADU];
    __shared__ unsigned Bs_lo[128 * PADU];

    const int tid = threadIdx.x;
    const int wid = tid >> 5, lane = tid & 31;
    const int wm = wid >> 2, wn = wid & 3;          // 2 x 4 warp grid
    const int m0 = blockIdx.y * 128, n0 = blockIdx.x * 128;
    const int lr = lane >> 2, lc = lane & 3;

    float acc[4][4][4];
#pragma unroll
    for (int mt = 0; mt < 4; mt++)
#pragma unroll
        for (int nt = 0; nt < 4; nt++)
#pragma unroll
            for (int i = 0; i < 4; i++) acc[mt][nt][i] = 0.f;

    for (int k0 = 0; k0 < K; k0 += 32) {
        __syncthreads();
#pragma unroll
        for (int t = 0; t < 4; t++) {
            int idx = tid + t * 256;        // 0..1023
            int r = idx >> 3;               // 0..127
            int c4 = (idx & 7) * 4;         // 0,4,..,28
            const float4 av = *(const float4*)(A + (size_t)(m0 + r) * K + k0 + c4);
            unsigned h0, l0, h1, l1;
            split2(av.x, av.y, h0, l0);
            split2(av.z, av.w, h1, l1);
            int sa = r * PADU + (c4 >> 1);
            As_hi[sa] = h0; As_hi[sa + 1] = h1;
            As_lo[sa] = l0; As_lo[sa + 1] = l1;
            const float4 bv = *(const float4*)(B + (size_t)(n0 + r) * K + k0 + c4);
            split2(bv.x, bv.y, h0, l0);
            split2(bv.z, bv.w, h1, l1);
            Bs_hi[sa] = h0; Bs_hi[sa + 1] = h1;
            Bs_lo[sa] = l0; Bs_lo[sa + 1] = l1;
        }
        __syncthreads();

#pragma unroll
        for (int kh = 0; kh < 2; kh++) {
            unsigned afh[4][4], afl[4][4];
#pragma unroll
            for (int mt = 0; mt < 4; mt++) {
                int r = wm * 64 + mt * 16 + lr;
                int base = r * PADU + kh * 8 + lc;
                afh[mt][0] = As_hi[base];
                afh[mt][1] = As_hi[base + 8 * PADU];
                afh[mt][2] = As_hi[base + 4];
                afh[mt][3] = As_hi[base + 8 * PADU + 4];
                afl[mt][0] = As_lo[base];
                afl[mt][1] = As_lo[base + 8 * PADU];
                afl[mt][2] = As_lo[base + 4];
                afl[mt][3] = As_lo[base + 8 * PADU + 4];
            }
#pragma unroll
            for (int nt = 0; nt < 4; nt++) {
                int n = wn * 32 + nt * 8 + lr;
                int base = n * PADU + kh * 8 + lc;
                unsigned bh0 = Bs_hi[base], bh1 = Bs_hi[base + 4];
                unsigned bl0 = Bs_lo[base], bl1 = Bs_lo[base + 4];
#pragma unroll
                for (int mt = 0; mt < 4; mt++) {
                    mma_bf16(acc[mt][nt], afh[mt], bh0, bh1);
                    mma_bf16(acc[mt][nt], afh[mt], bl0, bl1);
                    mma_bf16(acc[mt][nt], afl[mt], bh0, bh1);
                }
            }
        }
    }

    const int rbase = m0 + wm * 64 + lr;
    const int cbase = n0 + wn * 32 + lc * 2;

    if (EPI == 0) {
#pragma unroll
        for (int mt = 0; mt < 4; mt++)
#pragma unroll
            for (int nt = 0; nt < 4; nt++) {
                int r = rbase + mt * 16;
                int c = cbase + nt * 8;
                *(float2*)&C[(size_t)r * N + c] =
                    make_float2(acc[mt][nt][0], acc[mt][nt][1]);
                *(float2*)&C[(size_t)(r + 8) * N + c] =
                    make_float2(acc[mt][nt][2], acc[mt][nt][3]);
            }
    } else if (EPI == 1 || EPI == 2) {
        const float oscale = (EPI == 1) ? 0.125f : 1.0f;
        __nv_bfloat16* dh = (EPI == 1) ? g_qh : g_kh;
        __nv_bfloat16* dl = (EPI == 1) ? g_ql : g_kl;
#pragma unroll
        for (int nt = 0; nt < 4; nt++) {
            int c = cbase + nt * 8;
            int h = c >> 6;
            int j = (c & 63) >> 1;
            float invf = expf(-((float)(2 * j) * (1.0f / 64.0f)) * 9.210340371976184f);
#pragma unroll
            for (int mt = 0; mt < 4; mt++) {
#pragma unroll
                for (int half = 0; half < 2; half++) {
                    int r = rbase + mt * 16 + half * 8;
                    float x1 = acc[mt][nt][half * 2];
                    float x2 = acc[mt][nt][half * 2 + 1];
                    float s, cc;
                    sincosf((float)r * invf, &s, &cc);
                    float o1 = (x1 * cc - x2 * s) * oscale;
                    float o2 = (x1 * s + x2 * cc) * oscale;
                    size_t i1 = (size_t)r * DM + h * 64 + j;
                    __nv_bfloat16 bh, bl;
                    split1(o1, bh, bl); dh[i1] = bh; dl[i1] = bl;
                    split1(o2, bh, bl); dh[i1 + 32] = bh; dl[i1 + 32] = bl;
                }
            }
        }
    } else {  // EPI == 3 : V, split + transpose to [NH][HD][LL]
#pragma unroll
        for (int nt = 0; nt < 4; nt++) {
#pragma unroll
            for (int e = 0; e < 2; e++) {
                int c = cbase + nt * 8 + e;
                int h = c >> 6, w = c & 63;
                size_t colbase = (size_t)(h * 64 + w) * LL;
#pragma unroll
                for (int mt = 0; mt < 4; mt++) {
#pragma unroll
                    for (int half = 0; half < 2; half++) {
                        int r = rbase + mt * 16 + half * 8;
                        float x = acc[mt][nt][half * 2 + e];
                        __nv_bfloat16 bh, bl;
                        split1(x, bh, bl);
                        g_vth[colbase + r] = bh;
                        g_vtl[colbase + r] = bl;
                    }
                }
            }
        }
    }
}

// ---------------- Tensor-core flash attention --------------------------------
// Grid (32 q-tiles, 32 heads), 128 threads = 4 warps; warp owns 16 q rows.
// Q/K roped bf16 hi/lo; V transposed bf16 hi/lo. bf16x3 for S and PV.
#define QH0 0
#define QL0 (64 * AST)
#define KH0 (2 * 64 * AST)
#define KL0 (3 * 64 * AST)
#define VH0 (4 * 64 * AST)
#define VL0 (5 * 64 * AST)
#define MS0 (6 * 64 * AST)
#define FLASH_SMEM ((6 * 64 * AST + 64) * 4)

__global__ __launch_bounds__(128) void flash_mma(const int* __restrict__ mask)
{
    extern __shared__ unsigned sm[];
    int* smask = (int*)(sm + MS0);

    const int tid = threadIdx.x;
    const int warp = tid >> 5, lane = tid & 31;
    const int lr = lane >> 2, lc = lane & 3;
    const int head = blockIdx.y;
    const int q0 = blockIdx.x * 64;
    const int wq = warp * 16;

    const unsigned* Gqh = (const unsigned*)g_qh;
    const unsigned* Gql = (const unsigned*)g_ql;
    const unsigned* Gkh = (const unsigned*)g_kh;
    const unsigned* Gkl = (const unsigned*)g_kl;
    const unsigned* Gvh = (const unsigned*)g_vth;
    const unsigned* Gvl = (const unsigned*)g_vtl;

    // stage Q (64 rows x 32 u32)
    for (int idx = tid; idx < 2048; idx += 128) {
        int r = idx >> 5, c = idx & 31;
        int gi = (q0 + r) * 1024 + head * 32 + c;
        sm[QH0 + r * AST + c] = Gqh[gi];
        sm[QL0 + r * AST + c] = Gql[gi];
    }

    float o[8][4];
#pragma unroll
    for (int nt = 0; nt < 8; nt++)
#pragma unroll
        for (int i = 0; i < 4; i++) o[nt][i] = 0.f;
    float m0r = -INFINITY, m1r = -INFINITY;
    float l0r = 0.f, l1r = 0.f;

    for (int kt = 0; kt < LL / 64; kt++) {
        __syncthreads();
        for (int idx = tid; idx < 2048; idx += 128) {
            int r = idx >> 5, c = idx & 31;
            int gk = (kt * 64 + r) * 1024 + head * 32 + c;
            sm[KH0 + r * AST + c] = Gkh[gk];
            sm[KL0 + r * AST + c] = Gkl[gk];
            int gv = (head * 64 + r) * 1024 + kt * 32 + c;
            sm[VH0 + r * AST + c] = Gvh[gv];
            sm[VL0 + r * AST + c] = Gvl[gv];
        }
        if (tid < 64) smask[tid] = mask[kt * 64 + tid];
        __syncthreads();

        // ---- S = Q K^T (bf16x3) ----
        float s[8][4];
#pragma unroll
        for (int nt = 0; nt < 8; nt++)
#pragma unroll
            for (int i = 0; i < 4; i++) s[nt][i] = 0.f;

#pragma unroll
        for (int kc = 0; kc < 4; kc++) {
            unsigned qh[4], ql[4];
            int qb = (wq + lr) * AST + kc * 8 + lc;
            qh[0] = sm[QH0 + qb];            ql[0] = sm[QL0 + qb];
            qh[1] = sm[QH0 + qb + 8 * AST];  ql[1] = sm[QL0 + qb + 8 * AST];
            qh[2] = sm[QH0 + qb + 4];        ql[2] = sm[QL0 + qb + 4];
            qh[3] = sm[QH0 + qb + 8 * AST + 4]; ql[3] = sm[QL0 + qb + 8 * AST + 4];
#pragma unroll
            for (int nt = 0; nt < 8; nt++) {
                int kb = (nt * 8 + lr) * AST + kc * 8 + lc;
                unsigned bh0 = sm[KH0 + kb], bh1 = sm[KH0 + kb + 4];
                unsigned bl0 = sm[KL0 + kb], bl1 = sm[KL0 + kb + 4];
                mma_bf16(s[nt], qh, bh0, bh1);
                mma_bf16(s[nt], qh, bl0, bl1);
                mma_bf16(s[nt], ql, bh0, bh1);
            }
        }

        // ---- mask ----
#pragma unroll
        for (int nt = 0; nt < 8; nt++) {
            int c0 = nt * 8 + 2 * lc;
            if (smask[c0] == 0)     { s[nt][0] = -1e9f; s[nt][2] = -1e9f; }
            if (smask[c0 + 1] == 0) { s[nt][1] = -1e9f; s[nt][3] = -1e9f; }
        }

        // ---- online softmax (rows lr and lr+8; quad = lanes xor 1,2) ----
        float mx0 = -INFINITY, mx1 = -INFINITY;
#pragma unroll
        for (int nt = 0; nt < 8; nt++) {
            mx0 = fmaxf(mx0, fmaxf(s[nt][0], s[nt][1]));
            mx1 = fmaxf(mx1, fmaxf(s[nt][2], s[nt][3]));
        }
        mx0 = fmaxf(mx0, __shfl_xor_sync(0xffffffffu, mx0, 1));
        mx0 = fmaxf(mx0, __shfl_xor_sync(0xffffffffu, mx0, 2));
        mx1 = fmaxf(mx1, __shfl_xor_sync(0xffffffffu, mx1, 1));
        mx1 = fmaxf(mx1, __shfl_xor_sync(0xffffffffu, mx1, 2));
        float mn0 = fmaxf(m0r, mx0), mn1 = fmaxf(m1r, mx1);
        float a0 = __expf(m0r - mn0), a1 = __expf(m1r - mn1);
        m0r = mn0; m1r = mn1;
        float ps0 = 0.f, ps1 = 0.f;
#pragma unroll
        for (int nt = 0; nt < 8; nt++) {
            s[nt][0] = __expf(s[nt][0] - mn0);
            s[nt][1] = __expf(s[nt][1] - mn0);
            s[nt][2] = __expf(s[nt][2] - mn1);
            s[nt][3] = __expf(s[nt][3] - mn1);
            ps0 += s[nt][0] + s[nt][1];
            ps1 += s[nt][2] + s[nt][3];
        }
        l0r = l0r * a0 + ps0;
        l1r = l1r * a1 + ps1;
#pragma unroll
        for (int nt = 0; nt < 8; nt++) {
            o[nt][0] *= a0; o[nt][1] *= a0;
            o[nt][2] *= a1; o[nt][3] *= a1;
        }

        // ---- O += P V (P split hi/lo in registers; bf16x3) ----
#pragma unroll
        for (int kc = 0; kc < 4; kc++) {
            unsigned ph[4], pl[4];
            split2(s[2 * kc][0],     s[2 * kc][1],     ph[0], pl[0]);
            split2(s[2 * kc][2],     s[2 * kc][3],     ph[1], pl[1]);
            split2(s[2 * kc + 1][0], s[2 * kc + 1][1], ph[2], pl[2]);
            split2(s[2 * kc + 1][2], s[2 * kc + 1][3], ph[3], pl[3]);
#pragma unroll
            for (int nt = 0; nt < 8; nt++) {
                int vb = (nt * 8 + lr) * AST + kc * 8 + lc;
                unsigned vh0 = sm[VH0 + vb], vh1 = sm[VH0 + vb + 4];
                unsigned vl0 = sm[VL0 + vb], vl1 = sm[VL0 + vb + 4];
                mma_bf16(o[nt], ph, vh0, vh1);
                mma_bf16(o[nt], ph, vl0, vl1);
                mma_bf16(o[nt], pl, vh0, vh1);
            }
        }
    }

    // final: reduce l across quad, normalize, store
    l0r += __shfl_xor_sync(0xffffffffu, l0r, 1);
    l0r += __shfl_xor_sync(0xffffffffu, l0r, 2);
    l1r += __shfl_xor_sync(0xffffffffu, l1r, 1);
    l1r += __shfl_xor_sync(0xffffffffu, l1r, 2);
    float inv0 = 1.f / l0r, inv1 = 1.f / l1r;

    int r0 = q0 + wq + lr;
    int cb = head * 64 + 2 * lc;
#pragma unroll
    for (int nt = 0; nt < 8; nt++) {
        *(float2*)&g_attn[(size_t)r0 * DM + cb + nt * 8] =
            make_float2(o[nt][0] * inv0, o[nt][1] * inv0);
        *(float2*)&g_attn[(size_t)(r0 + 8) * DM + cb + nt * 8] =
            make_float2(o[nt][2] * inv1, o[nt][3] * inv1);
    }
}

// ---------------- launch ------------------------------------------------------
extern "C" void kernel_launch(void* const* d_in, const int* in_sizes, int n_in,
                              void* d_out, int out_size)
{
    const float* x = (const float*)d_in[0];
    const int* mask = (const int*)d_in[1];
    const float* Wq = (const float*)d_in[2];
    const float* Wk = (const float*)d_in[3];
    const float* Wv = (const float*)d_in[4];
    const float* Wo = (const float*)d_in[5];
    float* out = (float*)d_out;

    static float* attn = nullptr;
    if (!attn) {
        cudaGetSymbolAddress((void**)&attn, g_attn);
        cudaFuncSetAttribute(flash_mma,
                             cudaFuncAttributeMaxDynamicSharedMemorySize,
                             FLASH_SMEM);
    }

    dim3 gg(DM / 128, LL / 128);
    gemm_bf16x3<1><<<gg, 256>>>(x, Wq, nullptr, LL, DM, DM);
    gemm_bf16x3<2><<<gg, 256>>>(x, Wk, nullptr, LL, DM, DM);
    gemm_bf16x3<3><<<gg, 256>>>(x, Wv, nullptr, LL, DM, DM);

    flash_mma<<<dim3(LL / 64, NH), 128, FLASH_SMEM>>>(mask);

    gemm_bf16x3<0><<<gg, 256>>>(attn, Wo, out, LL, DM, DM);
}

// round 5
// speedup vs baseline: 2.8372x; 1.3505x over previous
#include <cuda_runtime.h>
#include <cuda_bf16.h>
#include <math.h>

#define LL 2048
#define DM 2048
#define NH 32
#define HD 64
#define PADU 20   // u32 row stride for GEMM bf16 smem (conflict-free frags)
#define AST 36    // u32 row stride for attention smem (bank = 4*lr+lc, distinct)

// ---------------- scratch (static device globals: allocation-free) -----------
__device__ float g_attn[LL * DM];
__device__ __nv_bfloat16 g_qh[LL * DM], g_ql[LL * DM];   // roped Q (hi/lo), scale folded
__device__ __nv_bfloat16 g_kh[LL * DM], g_kl[LL * DM];   // roped K (hi/lo)
__device__ __nv_bfloat16 g_vth[LL * DM], g_vtl[LL * DM]; // V transposed: [NH][HD][LL]

// ---------------- helpers ----------------------------------------------------
__device__ __forceinline__ unsigned sptr(const void* p)
{
    return (unsigned)__cvta_generic_to_shared(p);
}
__device__ __forceinline__ void cpa16(void* smem_dst, const void* gsrc)
{
    asm volatile("cp.async.cg.shared.global [%0], [%1], 16;\n"
                 :: "r"(sptr(smem_dst)), "l"(gsrc));
}
#define CP_COMMIT() asm volatile("cp.async.commit_group;\n" ::: "memory")
#define CP_WAIT(N)  asm volatile("cp.async.wait_group %0;\n" :: "n"(N) : "memory")

__device__ __forceinline__ void split2(float x, float y,
                                       unsigned& hi, unsigned& lo)
{
    __nv_bfloat16 hx = __float2bfloat16(x);
    __nv_bfloat16 hy = __float2bfloat16(y);
    float rx = x - __bfloat162float(hx);
    float ry = y - __bfloat162float(hy);
    __nv_bfloat162 h = __halves2bfloat162(hx, hy);
    __nv_bfloat162 l = __halves2bfloat162(__float2bfloat16(rx),
                                          __float2bfloat16(ry));
    hi = *reinterpret_cast<unsigned*>(&h);
    lo = *reinterpret_cast<unsigned*>(&l);
}

__device__ __forceinline__ void split1(float x, __nv_bfloat16& h, __nv_bfloat16& l)
{
    h = __float2bfloat16(x);
    l = __float2bfloat16(x - __bfloat162float(h));
}

__device__ __forceinline__ void mma_bf16(float* d, const unsigned* a,
                                         unsigned b0, unsigned b1)
{
    asm volatile(
        "mma.sync.aligned.m16n8k16.row.col.f32.bf16.bf16.f32 "
        "{%0,%1,%2,%3},{%4,%5,%6,%7},{%8,%9},{%0,%1,%2,%3};\n"
        : "+f"(d[0]), "+f"(d[1]), "+f"(d[2]), "+f"(d[3])
        : "r"(a[0]), "r"(a[1]), "r"(a[2]), "r"(a[3]), "r"(b0), "r"(b1));
}

// ---------------- bf16x3 tensor-core GEMM: C = A[M,K] * B[N,K]^T -------------
// cp.async pipeline: fp32 tile staged in smem, split to bf16 hi/lo, next tile's
// cp.async issued before the MMA section so LDG latency hides under compute.
// EPI 0: plain fp32 C.  EPI 1: rope+split -> g_qh/g_ql (scale 1/8).
// EPI 2: rope+split -> g_kh/g_kl.  EPI 3: split+per-head transpose -> g_vth/l.
#define GEMM_SMEM ((8192 + 4 * 128 * PADU) * 4)   // 73728 B

template <int EPI>
__global__ __launch_bounds__(256, 2) void gemm_bf16x3(
    const float* __restrict__ A, const float* __restrict__ B,
    float* __restrict__ C, int M, int N, int K)
{
    extern __shared__ unsigned char gsm[];
    float* stA = (float*)gsm;                   // 128*32 fp32
    float* stB = stA + 4096;                    // 128*32 fp32
    unsigned* As_hi = (unsigned*)(stB + 4096);  // 128*PADU each
    unsigned* As_lo = As_hi + 128 * PADU;
    unsigned* Bs_hi = As_lo + 128 * PADU;
    unsigned* Bs_lo = Bs_hi + 128 * PADU;

    const int tid = threadIdx.x;
    const int wid = tid >> 5, lane = tid & 31;
    const int wm = wid >> 2, wn = wid & 3;          // 2 x 4 warp grid
    const int m0 = blockIdx.y * 128, n0 = blockIdx.x * 128;
    const int lr = lane >> 2, lc = lane & 3;

    const int pr = tid >> 3;            // 0..31 (row within t-chunk)
    const int pc = (tid & 7) * 4;       // 0,4,..,28

    float acc[4][4][4];
#pragma unroll
    for (int mt = 0; mt < 4; mt++)
#pragma unroll
        for (int nt = 0; nt < 4; nt++)
#pragma unroll
            for (int i = 0; i < 4; i++) acc[mt][nt][i] = 0.f;

    // prologue: stage tile k0=0
#pragma unroll
    for (int t = 0; t < 4; t++) {
        int r = pr + t * 32;
        cpa16(stA + r * 32 + pc, A + (size_t)(m0 + r) * K + pc);
        cpa16(stB + r * 32 + pc, B + (size_t)(n0 + r) * K + pc);
    }
    CP_COMMIT();

    for (int k0 = 0; k0 < K; k0 += 32) {
        CP_WAIT(0);
        __syncthreads();                 // stage(k0) visible; bf16 smem free
        // split stage -> bf16 hi/lo smem
#pragma unroll
        for (int t = 0; t < 4; t++) {
            int r = pr + t * 32;
            float4 av = *(const float4*)(stA + r * 32 + pc);
            unsigned h0, l0, h1, l1;
            split2(av.x, av.y, h0, l0);
            split2(av.z, av.w, h1, l1);
            int sa = r * PADU + (pc >> 1);
            As_hi[sa] = h0; As_hi[sa + 1] = h1;
            As_lo[sa] = l0; As_lo[sa + 1] = l1;
            float4 bv = *(const float4*)(stB + r * 32 + pc);
            split2(bv.x, bv.y, h0, l0);
            split2(bv.z, bv.w, h1, l1);
            Bs_hi[sa] = h0; Bs_hi[sa + 1] = h1;
            Bs_lo[sa] = l0; Bs_lo[sa + 1] = l1;
        }
        __syncthreads();                 // bf16 ready; stage free

        if (k0 + 32 < K) {               // overlap next tile's LDG with MMAs
#pragma unroll
            for (int t = 0; t < 4; t++) {
                int r = pr + t * 32;
                cpa16(stA + r * 32 + pc, A + (size_t)(m0 + r) * K + k0 + 32 + pc);
                cpa16(stB + r * 32 + pc, B + (size_t)(n0 + r) * K + k0 + 32 + pc);
            }
            CP_COMMIT();
        }

#pragma unroll
        for (int kh = 0; kh < 2; kh++) {
            unsigned afh[4][4], afl[4][4];
#pragma unroll
            for (int mt = 0; mt < 4; mt++) {
                int r = wm * 64 + mt * 16 + lr;
                int base = r * PADU + kh * 8 + lc;
                afh[mt][0] = As_hi[base];
                afh[mt][1] = As_hi[base + 8 * PADU];
                afh[mt][2] = As_hi[base + 4];
                afh[mt][3] = As_hi[base + 8 * PADU + 4];
                afl[mt][0] = As_lo[base];
                afl[mt][1] = As_lo[base + 8 * PADU];
                afl[mt][2] = As_lo[base + 4];
                afl[mt][3] = As_lo[base + 8 * PADU + 4];
            }
#pragma unroll
            for (int nt = 0; nt < 4; nt++) {
                int n = wn * 32 + nt * 8 + lr;
                int base = n * PADU + kh * 8 + lc;
                unsigned bh0 = Bs_hi[base], bh1 = Bs_hi[base + 4];
                unsigned bl0 = Bs_lo[base], bl1 = Bs_lo[base + 4];
#pragma unroll
                for (int mt = 0; mt < 4; mt++) {
                    mma_bf16(acc[mt][nt], afh[mt], bh0, bh1);
                    mma_bf16(acc[mt][nt], afh[mt], bl0, bl1);
                    mma_bf16(acc[mt][nt], afl[mt], bh0, bh1);
                }
            }
        }
    }

    const int rbase = m0 + wm * 64 + lr;
    const int cbase = n0 + wn * 32 + lc * 2;

    if (EPI == 0) {
#pragma unroll
        for (int mt = 0; mt < 4; mt++)
#pragma unroll
            for (int nt = 0; nt < 4; nt++) {
                int r = rbase + mt * 16;
                int c = cbase + nt * 8;
                *(float2*)&C[(size_t)r * N + c] =
                    make_float2(acc[mt][nt][0], acc[mt][nt][1]);
                *(float2*)&C[(size_t)(r + 8) * N + c] =
                    make_float2(acc[mt][nt][2], acc[mt][nt][3]);
            }
    } else if (EPI == 1 || EPI == 2) {
        const float oscale = (EPI == 1) ? 0.125f : 1.0f;
        __nv_bfloat16* dh = (EPI == 1) ? g_qh : g_kh;
        __nv_bfloat16* dl = (EPI == 1) ? g_ql : g_kl;
#pragma unroll
        for (int nt = 0; nt < 4; nt++) {
            int c = cbase + nt * 8;
            int h = c >> 6;
            int j = (c & 63) >> 1;
            float invf = expf(-((float)(2 * j) * (1.0f / 64.0f)) * 9.210340371976184f);
#pragma unroll
            for (int mt = 0; mt < 4; mt++) {
#pragma unroll
                for (int half = 0; half < 2; half++) {
                    int r = rbase + mt * 16 + half * 8;
                    float x1 = acc[mt][nt][half * 2];
                    float x2 = acc[mt][nt][half * 2 + 1];
                    float s, cc;
                    sincosf((float)r * invf, &s, &cc);
                    float o1 = (x1 * cc - x2 * s) * oscale;
                    float o2 = (x1 * s + x2 * cc) * oscale;
                    size_t i1 = (size_t)r * DM + h * 64 + j;
                    __nv_bfloat16 bh, bl;
                    split1(o1, bh, bl); dh[i1] = bh; dl[i1] = bl;
                    split1(o2, bh, bl); dh[i1 + 32] = bh; dl[i1 + 32] = bl;
                }
            }
        }
    } else {  // EPI == 3 : V, split + transpose to [NH][HD][LL]
#pragma unroll
        for (int nt = 0; nt < 4; nt++) {
#pragma unroll
            for (int e = 0; e < 2; e++) {
                int c = cbase + nt * 8 + e;
                int h = c >> 6, w = c & 63;
                size_t colbase = (size_t)(h * 64 + w) * LL;
#pragma unroll
                for (int mt = 0; mt < 4; mt++) {
#pragma unroll
                    for (int half = 0; half < 2; half++) {
                        int r = rbase + mt * 16 + half * 8;
                        float x = acc[mt][nt][half * 2 + e];
                        __nv_bfloat16 bh, bl;
                        split1(x, bh, bl);
                        g_vth[colbase + r] = bh;
                        g_vtl[colbase + r] = bl;
                    }
                }
            }
        }
    }
}

// ---------------- Tensor-core flash attention --------------------------------
// Grid (32 q-tiles, 32 heads), 128 threads = 4 warps; warp owns 16 q rows.
// cp.async pipeline: K(t+1) copy overlaps softmax+PV(t); V(t+1) overlaps S(t+1).
#define QH0 0
#define QL0 (64 * AST)
#define KH0 (2 * 64 * AST)
#define KL0 (3 * 64 * AST)
#define VH0 (4 * 64 * AST)
#define VL0 (5 * 64 * AST)
#define FLASH_SMEM (6 * 64 * AST * 4)   // 55296 B

__global__ __launch_bounds__(128, 4) void flash_mma(const int* __restrict__ mask)
{
    extern __shared__ unsigned sm[];

    const int tid = threadIdx.x;
    const int warp = tid >> 5, lane = tid & 31;
    const int lr = lane >> 2, lc = lane & 3;
    const int head = blockIdx.y;
    const int q0 = blockIdx.x * 64;
    const int wq = warp * 16;

    const unsigned* Gqh = (const unsigned*)g_qh;
    const unsigned* Gql = (const unsigned*)g_ql;
    const unsigned* Gkh = (const unsigned*)g_kh;
    const unsigned* Gkl = (const unsigned*)g_kl;
    const unsigned* Gvh = (const unsigned*)g_vth;
    const unsigned* Gvl = (const unsigned*)g_vtl;

    const int pr = tid >> 3;            // 0..15
    const int pc = (tid & 7) * 4;       // 0,4,..,28

    // prologue: cp K(0) then V(0) (separate groups)
#pragma unroll
    for (int t = 0; t < 4; t++) {
        int r = pr + t * 16;
        int g = r * 1024 + head * 32 + pc;
        cpa16(&sm[KH0 + r * AST + pc], Gkh + g);
        cpa16(&sm[KL0 + r * AST + pc], Gkl + g);
    }
    CP_COMMIT();
#pragma unroll
    for (int t = 0; t < 4; t++) {
        int r = pr + t * 16;
        int g = (head * 64 + r) * 1024 + pc;
        cpa16(&sm[VH0 + r * AST + pc], Gvh + g);
        cpa16(&sm[VL0 + r * AST + pc], Gvl + g);
    }
    CP_COMMIT();

    // stage Q (plain loads; covered by first top-of-loop sync)
    for (int idx = tid; idx < 2048; idx += 128) {
        int r = idx >> 5, c = idx & 31;
        int gi = (q0 + r) * 1024 + head * 32 + c;
        sm[QH0 + r * AST + c] = Gqh[gi];
        sm[QL0 + r * AST + c] = Gql[gi];
    }

    float o[8][4];
#pragma unroll
    for (int nt = 0; nt < 8; nt++)
#pragma unroll
        for (int i = 0; i < 4; i++) o[nt][i] = 0.f;
    float m0r = -INFINITY, m1r = -INFINITY;
    float l0r = 0.f, l1r = 0.f;

    for (int kt = 0; kt < LL / 64; kt++) {
        CP_WAIT(1);                      // K(kt) arrived (V may be in flight)
        __syncthreads();

        // mask tile -> regs (no smem, overlaps S)
        int2 mreg[8];
#pragma unroll
        for (int nt = 0; nt < 8; nt++)
            mreg[nt] = *(const int2*)&mask[kt * 64 + nt * 8 + 2 * lc];

        // ---- S = Q K^T (bf16x3) ----
        float s[8][4];
#pragma unroll
        for (int nt = 0; nt < 8; nt++)
#pragma unroll
            for (int i = 0; i < 4; i++) s[nt][i] = 0.f;

#pragma unroll
        for (int kc = 0; kc < 4; kc++) {
            unsigned qh[4], ql[4];
            int qb = (wq + lr) * AST + kc * 8 + lc;
            qh[0] = sm[QH0 + qb];            ql[0] = sm[QL0 + qb];
            qh[1] = sm[QH0 + qb + 8 * AST];  ql[1] = sm[QL0 + qb + 8 * AST];
            qh[2] = sm[QH0 + qb + 4];        ql[2] = sm[QL0 + qb + 4];
            qh[3] = sm[QH0 + qb + 8 * AST + 4]; ql[3] = sm[QL0 + qb + 8 * AST + 4];
#pragma unroll
            for (int nt = 0; nt < 8; nt++) {
                int kb = (nt * 8 + lr) * AST + kc * 8 + lc;
                unsigned bh0 = sm[KH0 + kb], bh1 = sm[KH0 + kb + 4];
                unsigned bl0 = sm[KL0 + kb], bl1 = sm[KL0 + kb + 4];
                mma_bf16(s[nt], qh, bh0, bh1);
                mma_bf16(s[nt], qh, bl0, bl1);
                mma_bf16(s[nt], ql, bh0, bh1);
            }
        }

        CP_WAIT(0);                      // V(kt) arrived; K fully consumed
        __syncthreads();

        if (kt + 1 < LL / 64) {          // K(kt+1) overlaps softmax + PV
#pragma unroll
            for (int t = 0; t < 4; t++) {
                int r = pr + t * 16;
                int g = ((kt + 1) * 64 + r) * 1024 + head * 32 + pc;
                cpa16(&sm[KH0 + r * AST + pc], Gkh + g);
                cpa16(&sm[KL0 + r * AST + pc], Gkl + g);
            }
            CP_COMMIT();
        }

        // ---- mask ----
#pragma unroll
        for (int nt = 0; nt < 8; nt++) {
            if (mreg[nt].x == 0) { s[nt][0] = -1e9f; s[nt][2] = -1e9f; }
            if (mreg[nt].y == 0) { s[nt][1] = -1e9f; s[nt][3] = -1e9f; }
        }

        // ---- online softmax (rows lr and lr+8; quad = lanes xor 1,2) ----
        float mx0 = -INFINITY, mx1 = -INFINITY;
#pragma unroll
        for (int nt = 0; nt < 8; nt++) {
            mx0 = fmaxf(mx0, fmaxf(s[nt][0], s[nt][1]));
            mx1 = fmaxf(mx1, fmaxf(s[nt][2], s[nt][3]));
        }
        mx0 = fmaxf(mx0, __shfl_xor_sync(0xffffffffu, mx0, 1));
        mx0 = fmaxf(mx0, __shfl_xor_sync(0xffffffffu, mx0, 2));
        mx1 = fmaxf(mx1, __shfl_xor_sync(0xffffffffu, mx1, 1));
        mx1 = fmaxf(mx1, __shfl_xor_sync(0xffffffffu, mx1, 2));
        float mn0 = fmaxf(m0r, mx0), mn1 = fmaxf(m1r, mx1);
        float a0 = __expf(m0r - mn0), a1 = __expf(m1r - mn1);
        m0r = mn0; m1r = mn1;
        float ps0 = 0.f, ps1 = 0.f;
#pragma unroll
        for (int nt = 0; nt < 8; nt++) {
            s[nt][0] = __expf(s[nt][0] - mn0);
            s[nt][1] = __expf(s[nt][1] - mn0);
            s[nt][2] = __expf(s[nt][2] - mn1);
            s[nt][3] = __expf(s[nt][3] - mn1);
            ps0 += s[nt][0] + s[nt][1];
            ps1 += s[nt][2] + s[nt][3];
        }
        l0r = l0r * a0 + ps0;
        l1r = l1r * a1 + ps1;
#pragma unroll
        for (int nt = 0; nt < 8; nt++) {
            o[nt][0] *= a0; o[nt][1] *= a0;
            o[nt][2] *= a1; o[nt][3] *= a1;
        }

        // ---- O += P V (P split hi/lo in registers; bf16x3) ----
#pragma unroll
        for (int kc = 0; kc < 4; kc++) {
            unsigned ph[4], pl[4];
            split2(s[2 * kc][0],     s[2 * kc][1],     ph[0], pl[0]);
            split2(s[2 * kc][2],     s[2 * kc][3],     ph[1], pl[1]);
            split2(s[2 * kc + 1][0], s[2 * kc + 1][1], ph[2], pl[2]);
            split2(s[2 * kc + 1][2], s[2 * kc + 1][3], ph[3], pl[3]);
#pragma unroll
            for (int nt = 0; nt < 8; nt++) {
                int vb = (nt * 8 + lr) * AST + kc * 8 + lc;
                unsigned vh0 = sm[VH0 + vb], vh1 = sm[VH0 + vb + 4];
                unsigned vl0 = sm[VL0 + vb], vl1 = sm[VL0 + vb + 4];
                mma_bf16(o[nt], ph, vh0, vh1);
                mma_bf16(o[nt], ph, vl0, vl1);
                mma_bf16(o[nt], pl, vh0, vh1);
            }
        }

        __syncthreads();                 // V fully consumed

        if (kt + 1 < LL / 64) {          // V(kt+1) overlaps next S
#pragma unroll
            for (int t = 0; t < 4; t++) {
                int r = pr + t * 16;
                int g = (head * 64 + r) * 1024 + (kt + 1) * 32 + pc;
                cpa16(&sm[VH0 + r * AST + pc], Gvh + g);
                cpa16(&sm[VL0 + r * AST + pc], Gvl + g);
            }
            CP_COMMIT();
        }
    }

    // final: reduce l across quad, normalize, store
    l0r += __shfl_xor_sync(0xffffffffu, l0r, 1);
    l0r += __shfl_xor_sync(0xffffffffu, l0r, 2);
    l1r += __shfl_xor_sync(0xffffffffu, l1r, 1);
    l1r += __shfl_xor_sync(0xffffffffu, l1r, 2);
    float inv0 = 1.f / l0r, inv1 = 1.f / l1r;

    int r0 = q0 + wq + lr;
    int cb = head * 64 + 2 * lc;
#pragma unroll
    for (int nt = 0; nt < 8; nt++) {
        *(float2*)&g_attn[(size_t)r0 * DM + cb + nt * 8] =
            make_float2(o[nt][0] * inv0, o[nt][1] * inv0);
        *(float2*)&g_attn[(size_t)(r0 + 8) * DM + cb + nt * 8] =
            make_float2(o[nt][2] * inv1, o[nt][3] * inv1);
    }
}

// ---------------- launch ------------------------------------------------------
extern "C" void kernel_launch(void* const* d_in, const int* in_sizes, int n_in,
                              void* d_out, int out_size)
{
    const float* x = (const float*)d_in[0];
    const int* mask = (const int*)d_in[1];
    const float* Wq = (const float*)d_in[2];
    const float* Wk = (const float*)d_in[3];
    const float* Wv = (const float*)d_in[4];
    const float* Wo = (const float*)d_in[5];
    float* out = (float*)d_out;

    static float* attn = nullptr;
    if (!attn) {
        cudaGetSymbolAddress((void**)&attn, g_attn);
        cudaFuncSetAttribute(flash_mma,
                             cudaFuncAttributeMaxDynamicSharedMemorySize,
                             FLASH_SMEM);
        cudaFuncSetAttribute(gemm_bf16x3<0>,
                             cudaFuncAttributeMaxDynamicSharedMemorySize,
                             GEMM_SMEM);
        cudaFuncSetAttribute(gemm_bf16x3<1>,
                             cudaFuncAttributeMaxDynamicSharedMemorySize,
                             GEMM_SMEM);
        cudaFuncSetAttribute(gemm_bf16x3<2>,
                             cudaFuncAttributeMaxDynamicSharedMemorySize,
                             GEMM_SMEM);
        cudaFuncSetAttribute(gemm_bf16x3<3>,
                             cudaFuncAttributeMaxDynamicSharedMemorySize,
                             GEMM_SMEM);
    }

    dim3 gg(DM / 128, LL / 128);
    gemm_bf16x3<1><<<gg, 256, GEMM_SMEM>>>(x, Wq, nullptr, LL, DM, DM);
    gemm_bf16x3<2><<<gg, 256, GEMM_SMEM>>>(x, Wk, nullptr, LL, DM, DM);
    gemm_bf16x3<3><<<gg, 256, GEMM_SMEM>>>(x, Wv, nullptr, LL, DM, DM);

    flash_mma<<<dim3(LL / 64, NH), 128, FLASH_SMEM>>>(mask);

    gemm_bf16x3<0><<<gg, 256, GEMM_SMEM>>>(attn, Wo, out, LL, DM, DM);
}

// round 6
// speedup vs baseline: 2.8388x; 1.0006x over previous
#include <cuda_runtime.h>
#include <cuda_bf16.h>
#include <math.h>

#define LL 2048
#define DM 2048
#define NH 32
#define HD 64
#define PADU 20   // u32 row stride for GEMM bf16 smem (conflict-free frags)
#define AST 36    // u32 row stride for attention smem (bank = 4*lr+lc, distinct)

// ---------------- scratch (static device globals: allocation-free) -----------
__device__ float g_attn[LL * DM];
__device__ __nv_bfloat16 g_qh[LL * DM], g_ql[LL * DM];   // roped Q (hi/lo), scale folded
__device__ __nv_bfloat16 g_kh[LL * DM], g_kl[LL * DM];   // roped K (hi/lo)
__device__ __nv_bfloat16 g_vth[LL * DM], g_vtl[LL * DM]; // V transposed: [NH][HD][LL]

// ---------------- helpers ----------------------------------------------------
__device__ __forceinline__ unsigned sptr(const void* p)
{
    return (unsigned)__cvta_generic_to_shared(p);
}
__device__ __forceinline__ void cpa16(void* smem_dst, const void* gsrc)
{
    asm volatile("cp.async.cg.shared.global [%0], [%1], 16;\n"
                 :: "r"(sptr(smem_dst)), "l"(gsrc));
}
#define CP_COMMIT() asm volatile("cp.async.commit_group;\n" ::: "memory")
#define CP_WAIT(N)  asm volatile("cp.async.wait_group %0;\n" :: "n"(N) : "memory")

__device__ __forceinline__ void split2(float x, float y,
                                       unsigned& hi, unsigned& lo)
{
    __nv_bfloat16 hx = __float2bfloat16(x);
    __nv_bfloat16 hy = __float2bfloat16(y);
    float rx = x - __bfloat162float(hx);
    float ry = y - __bfloat162float(hy);
    __nv_bfloat162 h = __halves2bfloat162(hx, hy);
    __nv_bfloat162 l = __halves2bfloat162(__float2bfloat16(rx),
                                          __float2bfloat16(ry));
    hi = *reinterpret_cast<unsigned*>(&h);
    lo = *reinterpret_cast<unsigned*>(&l);
}

__device__ __forceinline__ void split1(float x, __nv_bfloat16& h, __nv_bfloat16& l)
{
    h = __float2bfloat16(x);
    l = __float2bfloat16(x - __bfloat162float(h));
}

__device__ __forceinline__ void mma_bf16(float* d, const unsigned* a,
                                         unsigned b0, unsigned b1)
{
    asm volatile(
        "mma.sync.aligned.m16n8k16.row.col.f32.bf16.bf16.f32 "
        "{%0,%1,%2,%3},{%4,%5,%6,%7},{%8,%9},{%0,%1,%2,%3};\n"
        : "+f"(d[0]), "+f"(d[1]), "+f"(d[2]), "+f"(d[3])
        : "r"(a[0]), "r"(a[1]), "r"(a[2]), "r"(a[3]), "r"(b0), "r"(b1));
}

// ---------------- bf16x3 tensor-core GEMM: C = A[M,K] * B[N,K]^T -------------
// cp.async pipeline: fp32 tile staged in smem, split to bf16 hi/lo, next tile's
// cp.async issued before the MMA section so LDG latency hides under compute.
// EPI 0: plain fp32 C.  EPI 1: rope+split -> g_qh/g_ql (scale 1/8).
// EPI 2: rope+split -> g_kh/g_kl.  EPI 3: split+per-head transpose -> g_vth/l.
#define GEMM_SMEM ((8192 + 4 * 128 * PADU) * 4)   // 73728 B

template <int EPI>
__global__ __launch_bounds__(256, 2) void gemm_bf16x3(
    const float* __restrict__ A, const float* __restrict__ B,
    float* __restrict__ C, int M, int N, int K)
{
    extern __shared__ unsigned char gsm[];
    float* stA = (float*)gsm;                   // 128*32 fp32
    float* stB = stA + 4096;                    // 128*32 fp32
    unsigned* As_hi = (unsigned*)(stB + 4096);  // 128*PADU each
    unsigned* As_lo = As_hi + 128 * PADU;
    unsigned* Bs_hi = As_lo + 128 * PADU;
    unsigned* Bs_lo = Bs_hi + 128 * PADU;

    const int tid = threadIdx.x;
    const int wid = tid >> 5, lane = tid & 31;
    const int wm = wid >> 2, wn = wid & 3;          // 2 x 4 warp grid
    const int m0 = blockIdx.y * 128, n0 = blockIdx.x * 128;
    const int lr = lane >> 2, lc = lane & 3;

    const int pr = tid >> 3;            // 0..31 (row within t-chunk)
    const int pc = (tid & 7) * 4;       // 0,4,..,28

    float acc[4][4][4];
#pragma unroll
    for (int mt = 0; mt < 4; mt++)
#pragma unroll
        for (int nt = 0; nt < 4; nt++)
#pragma unroll
            for (int i = 0; i < 4; i++) acc[mt][nt][i] = 0.f;

    // prologue: stage tile k0=0
#pragma unroll
    for (int t = 0; t < 4; t++) {
        int r = pr + t * 32;
        cpa16(stA + r * 32 + pc, A + (size_t)(m0 + r) * K + pc);
        cpa16(stB + r * 32 + pc, B + (size_t)(n0 + r) * K + pc);
    }
    CP_COMMIT();

    for (int k0 = 0; k0 < K; k0 += 32) {
        CP_WAIT(0);
        __syncthreads();                 // stage(k0) visible; bf16 smem free
        // split stage -> bf16 hi/lo smem
#pragma unroll
        for (int t = 0; t < 4; t++) {
            int r = pr + t * 32;
            float4 av = *(const float4*)(stA + r * 32 + pc);
            unsigned h0, l0, h1, l1;
            split2(av.x, av.y, h0, l0);
            split2(av.z, av.w, h1, l1);
            int sa = r * PADU + (pc >> 1);
            As_hi[sa] = h0; As_hi[sa + 1] = h1;
            As_lo[sa] = l0; As_lo[sa + 1] = l1;
            float4 bv = *(const float4*)(stB + r * 32 + pc);
            split2(bv.x, bv.y, h0, l0);
            split2(bv.z, bv.w, h1, l1);
            Bs_hi[sa] = h0; Bs_hi[sa + 1] = h1;
            Bs_lo[sa] = l0; Bs_lo[sa + 1] = l1;
        }
        __syncthreads();                 // bf16 ready; stage free

        if (k0 + 32 < K) {               // overlap next tile's LDG with MMAs
#pragma unroll
            for (int t = 0; t < 4; t++) {
                int r = pr + t * 32;
                cpa16(stA + r * 32 + pc, A + (size_t)(m0 + r) * K + k0 + 32 + pc);
                cpa16(stB + r * 32 + pc, B + (size_t)(n0 + r) * K + k0 + 32 + pc);
            }
            CP_COMMIT();
        }

#pragma unroll
        for (int kh = 0; kh < 2; kh++) {
            unsigned afh[4][4], afl[4][4];
#pragma unroll
            for (int mt = 0; mt < 4; mt++) {
                int r = wm * 64 + mt * 16 + lr;
                int base = r * PADU + kh * 8 + lc;
                afh[mt][0] = As_hi[base];
                afh[mt][1] = As_hi[base + 8 * PADU];
                afh[mt][2] = As_hi[base + 4];
                afh[mt][3] = As_hi[base + 8 * PADU + 4];
                afl[mt][0] = As_lo[base];
                afl[mt][1] = As_lo[base + 8 * PADU];
                afl[mt][2] = As_lo[base + 4];
                afl[mt][3] = As_lo[base + 8 * PADU + 4];
            }
#pragma unroll
            for (int nt = 0; nt < 4; nt++) {
                int n = wn * 32 + nt * 8 + lr;
                int base = n * PADU + kh * 8 + lc;
                unsigned bh0 = Bs_hi[base], bh1 = Bs_hi[base + 4];
                unsigned bl0 = Bs_lo[base], bl1 = Bs_lo[base + 4];
#pragma unroll
                for (int mt = 0; mt < 4; mt++) {
                    mma_bf16(acc[mt][nt], afh[mt], bh0, bh1);
                    mma_bf16(acc[mt][nt], afh[mt], bl0, bl1);
                    mma_bf16(acc[mt][nt], afl[mt], bh0, bh1);
                }
            }
        }
    }

    const int rbase = m0 + wm * 64 + lr;
    const int cbase = n0 + wn * 32 + lc * 2;

    if (EPI == 0) {
#pragma unroll
        for (int mt = 0; mt < 4; mt++)
#pragma unroll
            for (int nt = 0; nt < 4; nt++) {
                int r = rbase + mt * 16;
                int c = cbase + nt * 8;
                *(float2*)&C[(size_t)r * N + c] =
                    make_float2(acc[mt][nt][0], acc[mt][nt][1]);
                *(float2*)&C[(size_t)(r + 8) * N + c] =
                    make_float2(acc[mt][nt][2], acc[mt][nt][3]);
            }
    } else if (EPI == 1 || EPI == 2) {
        const float oscale = (EPI == 1) ? 0.125f : 1.0f;
        __nv_bfloat16* dh = (EPI == 1) ? g_qh : g_kh;
        __nv_bfloat16* dl = (EPI == 1) ? g_ql : g_kl;
#pragma unroll
        for (int nt = 0; nt < 4; nt++) {
            int c = cbase + nt * 8;
            int h = c >> 6;
            int j = (c & 63) >> 1;
            float invf = expf(-((float)(2 * j) * (1.0f / 64.0f)) * 9.210340371976184f);
#pragma unroll
            for (int mt = 0; mt < 4; mt++) {
#pragma unroll
                for (int half = 0; half < 2; half++) {
                    int r = rbase + mt * 16 + half * 8;
                    float x1 = acc[mt][nt][half * 2];
                    float x2 = acc[mt][nt][half * 2 + 1];
                    float s, cc;
                    sincosf((float)r * invf, &s, &cc);
                    float o1 = (x1 * cc - x2 * s) * oscale;
                    float o2 = (x1 * s + x2 * cc) * oscale;
                    size_t i1 = (size_t)r * DM + h * 64 + j;
                    __nv_bfloat16 bh, bl;
                    split1(o1, bh, bl); dh[i1] = bh; dl[i1] = bl;
                    split1(o2, bh, bl); dh[i1 + 32] = bh; dl[i1 + 32] = bl;
                }
            }
        }
    } else {  // EPI == 3 : V, split + transpose to [NH][HD][LL]
#pragma unroll
        for (int nt = 0; nt < 4; nt++) {
#pragma unroll
            for (int e = 0; e < 2; e++) {
                int c = cbase + nt * 8 + e;
                int h = c >> 6, w = c & 63;
                size_t colbase = (size_t)(h * 64 + w) * LL;
#pragma unroll
                for (int mt = 0; mt < 4; mt++) {
#pragma unroll
                    for (int half = 0; half < 2; half++) {
                        int r = rbase + mt * 16 + half * 8;
                        float x = acc[mt][nt][half * 2 + e];
                        __nv_bfloat16 bh, bl;
                        split1(x, bh, bl);
                        g_vth[colbase + r] = bh;
                        g_vtl[colbase + r] = bl;
                    }
                }
            }
        }
    }
}

// ---------------- Tensor-core flash attention --------------------------------
// Grid (32 q-tiles, 32 heads), 128 threads = 4 warps; warp owns 16 q rows.
// cp.async pipeline: K(t+1) copy overlaps softmax+PV(t); V(t+1) overlaps S(t+1).
#define QH0 0
#define QL0 (64 * AST)
#define KH0 (2 * 64 * AST)
#define KL0 (3 * 64 * AST)
#define VH0 (4 * 64 * AST)
#define VL0 (5 * 64 * AST)
#define FLASH_SMEM (6 * 64 * AST * 4)   // 55296 B

__global__ __launch_bounds__(128, 4) void flash_mma(const int* __restrict__ mask)
{
    extern __shared__ unsigned sm[];

    const int tid = threadIdx.x;
    const int warp = tid >> 5, lane = tid & 31;
    const int lr = lane >> 2, lc = lane & 3;
    const int head = blockIdx.y;
    const int q0 = blockIdx.x * 64;
    const int wq = warp * 16;

    const unsigned* Gqh = (const unsigned*)g_qh;
    const unsigned* Gql = (const unsigned*)g_ql;
    const unsigned* Gkh = (const unsigned*)g_kh;
    const unsigned* Gkl = (const unsigned*)g_kl;
    const unsigned* Gvh = (const unsigned*)g_vth;
    const unsigned* Gvl = (const unsigned*)g_vtl;

    const int pr = tid >> 3;            // 0..15
    const int pc = (tid & 7) * 4;       // 0,4,..,28

    // prologue: cp K(0) then V(0) (separate groups)
#pragma unroll
    for (int t = 0; t < 4; t++) {
        int r = pr + t * 16;
        int g = r * 1024 + head * 32 + pc;
        cpa16(&sm[KH0 + r * AST + pc], Gkh + g);
        cpa16(&sm[KL0 + r * AST + pc], Gkl + g);
    }
    CP_COMMIT();
#pragma unroll
    for (int t = 0; t < 4; t++) {
        int r = pr + t * 16;
        int g = (head * 64 + r) * 1024 + pc;
        cpa16(&sm[VH0 + r * AST + pc], Gvh + g);
        cpa16(&sm[VL0 + r * AST + pc], Gvl + g);
    }
    CP_COMMIT();

    // stage Q (plain loads; covered by first top-of-loop sync)
    for (int idx = tid; idx < 2048; idx += 128) {
        int r = idx >> 5, c = idx & 31;
        int gi = (q0 + r) * 1024 + head * 32 + c;
        sm[QH0 + r * AST + c] = Gqh[gi];
        sm[QL0 + r * AST + c] = Gql[gi];
    }

    float o[8][4];
#pragma unroll
    for (int nt = 0; nt < 8; nt++)
#pragma unroll
        for (int i = 0; i < 4; i++) o[nt][i] = 0.f;
    float m0r = -INFINITY, m1r = -INFINITY;
    float l0r = 0.f, l1r = 0.f;

    for (int kt = 0; kt < LL / 64; kt++) {
        CP_WAIT(1);                      // K(kt) arrived (V may be in flight)
        __syncthreads();

        // mask tile -> regs (no smem, overlaps S)
        int2 mreg[8];
#pragma unroll
        for (int nt = 0; nt < 8; nt++)
            mreg[nt] = *(const int2*)&mask[kt * 64 + nt * 8 + 2 * lc];

        // ---- S = Q K^T (bf16x3) ----
        float s[8][4];
#pragma unroll
        for (int nt = 0; nt < 8; nt++)
#pragma unroll
            for (int i = 0; i < 4; i++) s[nt][i] = 0.f;

#pragma unroll
        for (int kc = 0; kc < 4; kc++) {
            unsigned qh[4], ql[4];
            int qb = (wq + lr) * AST + kc * 8 + lc;
            qh[0] = sm[QH0 + qb];            ql[0] = sm[QL0 + qb];
            qh[1] = sm[QH0 + qb + 8 * AST];  ql[1] = sm[QL0 + qb + 8 * AST];
            qh[2] = sm[QH0 + qb + 4];        ql[2] = sm[QL0 + qb + 4];
            qh[3] = sm[QH0 + qb + 8 * AST + 4]; ql[3] = sm[QL0 + qb + 8 * AST + 4];
#pragma unroll
            for (int nt = 0; nt < 8; nt++) {
                int kb = (nt * 8 + lr) * AST + kc * 8 + lc;
                unsigned bh0 = sm[KH0 + kb], bh1 = sm[KH0 + kb + 4];
                unsigned bl0 = sm[KL0 + kb], bl1 = sm[KL0 + kb + 4];
                mma_bf16(s[nt], qh, bh0, bh1);
                mma_bf16(s[nt], qh, bl0, bl1);
                mma_bf16(s[nt], ql, bh0, bh1);
            }
        }

        CP_WAIT(0);                      // V(kt) arrived; K fully consumed
        __syncthreads();

        if (kt + 1 < LL / 64) {          // K(kt+1) overlaps softmax + PV
#pragma unroll
            for (int t = 0; t < 4; t++) {
                int r = pr + t * 16;
                int g = ((kt + 1) * 64 + r) * 1024 + head * 32 + pc;
                cpa16(&sm[KH0 + r * AST + pc], Gkh + g);
                cpa16(&sm[KL0 + r * AST + pc], Gkl + g);
            }
            CP_COMMIT();
        }

        // ---- mask ----
#pragma unroll
        for (int nt = 0; nt < 8; nt++) {
            if (mreg[nt].x == 0) { s[nt][0] = -1e9f; s[nt][2] = -1e9f; }
            if (mreg[nt].y == 0) { s[nt][1] = -1e9f; s[nt][3] = -1e9f; }
        }

        // ---- online softmax (rows lr and lr+8; quad = lanes xor 1,2) ----
        float mx0 = -INFINITY, mx1 = -INFINITY;
#pragma unroll
        for (int nt = 0; nt < 8; nt++) {
            mx0 = fmaxf(mx0, fmaxf(s[nt][0], s[nt][1]));
            mx1 = fmaxf(mx1, fmaxf(s[nt][2], s[nt][3]));
        }
        mx0 = fmaxf(mx0, __shfl_xor_sync(0xffffffffu, mx0, 1));
        mx0 = fmaxf(mx0, __shfl_xor_sync(0xffffffffu, mx0, 2));
        mx1 = fmaxf(mx1, __shfl_xor_sync(0xffffffffu, mx1, 1));
        mx1 = fmaxf(mx1, __shfl_xor_sync(0xffffffffu, mx1, 2));
        float mn0 = fmaxf(m0r, mx0), mn1 = fmaxf(m1r, mx1);
        float a0 = __expf(m0r - mn0), a1 = __expf(m1r - mn1);
        m0r = mn0; m1r = mn1;
        float ps0 = 0.f, ps1 = 0.f;
#pragma unroll
        for (int nt = 0; nt < 8; nt++) {
            s[nt][0] = __expf(s[nt][0] - mn0);
            s[nt][1] = __expf(s[nt][1] - mn0);
            s[nt][2] = __expf(s[nt][2] - mn1);
            s[nt][3] = __expf(s[nt][3] - mn1);
            ps0 += s[nt][0] + s[nt][1];
            ps1 += s[nt][2] + s[nt][3];
        }
        l0r = l0r * a0 + ps0;
        l1r = l1r * a1 + ps1;
#pragma unroll
        for (int nt = 0; nt < 8; nt++) {
            o[nt][0] *= a0; o[nt][1] *= a0;
            o[nt][2] *= a1; o[nt][3] *= a1;
        }

        // ---- O += P V (P split hi/lo in registers; bf16x3) ----
#pragma unroll
        for (int kc = 0; kc < 4; kc++) {
            unsigned ph[4], pl[4];
            split2(s[2 * kc][0],     s[2 * kc][1],     ph[0], pl[0]);
            split2(s[2 * kc][2],     s[2 * kc][3],     ph[1], pl[1]);
            split2(s[2 * kc + 1][0], s[2 * kc + 1][1], ph[2], pl[2]);
            split2(s[2 * kc + 1][2], s[2 * kc + 1][3], ph[3], pl[3]);
#pragma unroll
            for (int nt = 0; nt < 8; nt++) {
                int vb = (nt * 8 + lr) * AST + kc * 8 + lc;
                unsigned vh0 = sm[VH0 + vb], vh1 = sm[VH0 + vb + 4];
                unsigned vl0 = sm[VL0 + vb], vl1 = sm[VL0 + vb + 4];
                mma_bf16(o[nt], ph, vh0, vh1);
                mma_bf16(o[nt], ph, vl0, vl1);
                mma_bf16(o[nt], pl, vh0, vh1);
            }
        }

        __syncthreads();                 // V fully consumed

        if (kt + 1 < LL / 64) {          // V(kt+1) overlaps next S
#pragma unroll
            for (int t = 0; t < 4; t++) {
                int r = pr + t * 16;
                int g = (head * 64 + r) * 1024 + (kt + 1) * 32 + pc;
                cpa16(&sm[VH0 + r * AST + pc], Gvh + g);
                cpa16(&sm[VL0 + r * AST + pc], Gvl + g);
            }
            CP_COMMIT();
        }
    }

    // final: reduce l across quad, normalize, store
    l0r += __shfl_xor_sync(0xffffffffu, l0r, 1);
    l0r += __shfl_xor_sync(0xffffffffu, l0r, 2);
    l1r += __shfl_xor_sync(0xffffffffu, l1r, 1);
    l1r += __shfl_xor_sync(0xffffffffu, l1r, 2);
    float inv0 = 1.f / l0r, inv1 = 1.f / l1r;

    int r0 = q0 + wq + lr;
    int cb = head * 64 + 2 * lc;
#pragma unroll
    for (int nt = 0; nt < 8; nt++) {
        *(float2*)&g_attn[(size_t)r0 * DM + cb + nt * 8] =
            make_float2(o[nt][0] * inv0, o[nt][1] * inv0);
        *(float2*)&g_attn[(size_t)(r0 + 8) * DM + cb + nt * 8] =
            make_float2(o[nt][2] * inv1, o[nt][3] * inv1);
    }
}

// ---------------- launch ------------------------------------------------------
extern "C" void kernel_launch(void* const* d_in, const int* in_sizes, int n_in,
                              void* d_out, int out_size)
{
    const float* x = (const float*)d_in[0];
    const int* mask = (const int*)d_in[1];
    const float* Wq = (const float*)d_in[2];
    const float* Wk = (const float*)d_in[3];
    const float* Wv = (const float*)d_in[4];
    const float* Wo = (const float*)d_in[5];
    float* out = (float*)d_out;

    static float* attn = nullptr;
    if (!attn) {
        cudaGetSymbolAddress((void**)&attn, g_attn);
        cudaFuncSetAttribute(flash_mma,
                             cudaFuncAttributeMaxDynamicSharedMemorySize,
                             FLASH_SMEM);
        cudaFuncSetAttribute(gemm_bf16x3<0>,
                             cudaFuncAttributeMaxDynamicSharedMemorySize,
                             GEMM_SMEM);
        cudaFuncSetAttribute(gemm_bf16x3<1>,
                             cudaFuncAttributeMaxDynamicSharedMemorySize,
                             GEMM_SMEM);
        cudaFuncSetAttribute(gemm_bf16x3<2>,
                             cudaFuncAttributeMaxDynamicSharedMemorySize,
                             GEMM_SMEM);
        cudaFuncSetAttribute(gemm_bf16x3<3>,
                             cudaFuncAttributeMaxDynamicSharedMemorySize,
                             GEMM_SMEM);
    }

    dim3 gg(DM / 128, LL / 128);
    gemm_bf16x3<1><<<gg, 256, GEMM_SMEM>>>(x, Wq, nullptr, LL, DM, DM);
    gemm_bf16x3<2><<<gg, 256, GEMM_SMEM>>>(x, Wk, nullptr, LL, DM, DM);
    gemm_bf16x3<3><<<gg, 256, GEMM_SMEM>>>(x, Wv, nullptr, LL, DM, DM);

    flash_mma<<<dim3(LL / 64, NH), 128, FLASH_SMEM>>>(mask);

    gemm_bf16x3<0><<<gg, 256, GEMM_SMEM>>>(attn, Wo, out, LL, DM, DM);
}